// round 17
// baseline (speedup 1.0000x reference)
#include <cuda_runtime.h>
#include <cuda_fp16.h>
#include <stdint.h>
#include <math.h>

#define kD 256
#define kH 8
#define kL 3
#define kB 32768
#define kMB 8
#define kNT 256
#define HS 264    // A-operand half stride
#define XSD 260   // xs float stride
#define QS 392    // qkv fp16 stride (4 heads * 96 + pad)

#define XO 0
#define HAO 33280
#define QOF 50176
#define OOF 75264
#define SMEM_BYTES 92160

// Weights pre-swizzled into mma.m16n8k16 B-fragment order:
// [tile][k16][lane][4 halves]  where the 4 halves are exactly lane's {b0,b1}.
__device__ __align__(16) __half g_WqkvF[kL * 96 * 16 * 32 * 4];  // gathered head order
__device__ __align__(16) __half g_WoF[kL * 32 * 16 * 32 * 4];
__device__ __align__(16) __half g_W1F[kL * 32 * 16 * 32 * 4];
__device__ __align__(16) __half g_W2F[kL * 32 * 16 * 32 * 4];

__global__ void prep_weights_kernel(const float* __restrict__ wqkv,
                                    const float* __restrict__ wo,
                                    const float* __restrict__ w1,
                                    const float* __restrict__ w2) {
  int idx = blockIdx.x * blockDim.x + threadIdx.x;
  const int SQ = kL * 96 * 16 * 32;
  const int SO = kL * 32 * 16 * 32;
  if (idx < SQ) {
    int lane = idx & 31, kk = (idx >> 5) & 15, tl = idx >> 9;
    int t = tl % 96, l = tl / 96;
    int head = t / 12, jm = t % 12, part = jm >> 2, sub = jm & 3;
    int col = part * 256 + head * 32 + sub * 8 + (lane >> 2);
    int kr = kk * 16 + (lane & 3) * 2;
    const float* src = wqkv + (size_t)l * 256 * 768;
    __half* dst = g_WqkvF + (size_t)idx * 4;
    dst[0] = __float2half_rn(src[(size_t)kr * 768 + col]);
    dst[1] = __float2half_rn(src[(size_t)(kr + 1) * 768 + col]);
    dst[2] = __float2half_rn(src[(size_t)(kr + 8) * 768 + col]);
    dst[3] = __float2half_rn(src[(size_t)(kr + 9) * 768 + col]);
    return;
  }
  idx -= SQ;
  if (idx >= 3 * SO) return;
  int which = idx / SO;
  int r = idx - which * SO;
  const float* srcA = (which == 0) ? wo : (which == 1) ? w1 : w2;
  __half* dstA = (which == 0) ? g_WoF : (which == 1) ? g_W1F : g_W2F;
  int lane = r & 31, kk = (r >> 5) & 15, tl = r >> 9;
  int t = tl & 31, l = tl >> 5;
  int col = t * 8 + (lane >> 2);
  int kr = kk * 16 + (lane & 3) * 2;
  const float* src = srcA + (size_t)l * 256 * 256;
  __half* dst = dstA + (size_t)r * 4;
  dst[0] = __float2half_rn(src[(size_t)kr * 256 + col]);
  dst[1] = __float2half_rn(src[(size_t)(kr + 1) * 256 + col]);
  dst[2] = __float2half_rn(src[(size_t)(kr + 8) * 256 + col]);
  dst[3] = __float2half_rn(src[(size_t)(kr + 9) * 256 + col]);
}

__device__ __forceinline__ uint32_t smem_u32(const void* p) {
  uint32_t a;
  asm volatile("{ .reg .u64 t; cvta.to.shared.u64 t, %1; cvt.u32.u64 %0, t; }"
               : "=r"(a) : "l"(p));
  return a;
}
__device__ __forceinline__ void ldsm4(uint32_t& r0, uint32_t& r1, uint32_t& r2,
                                      uint32_t& r3, uint32_t a) {
  asm volatile("ldmatrix.sync.aligned.m8n8.x4.shared.b16 {%0,%1,%2,%3}, [%4];"
               : "=r"(r0), "=r"(r1), "=r"(r2), "=r"(r3) : "r"(a));
}
__device__ __forceinline__ void mma16816(float* c, uint32_t a0, uint32_t a1,
                                         uint32_t a2, uint32_t a3, uint32_t b0,
                                         uint32_t b1) {
  asm volatile(
      "mma.sync.aligned.m16n8k16.row.col.f32.f16.f16.f32 "
      "{%0,%1,%2,%3}, {%4,%5,%6,%7}, {%8,%9}, {%0,%1,%2,%3};"
      : "+f"(c[0]), "+f"(c[1]), "+f"(c[2]), "+f"(c[3])
      : "r"(a0), "r"(a1), "r"(a2), "r"(a3), "r"(b0), "r"(b1));
}

// C[16, NT*8] += A[16,256](smem, one row band) @ W(fragment gmem).
// One ldsm4 per k-step; B streamed gmem->regs with distance-2 prefetch.
template <int NT>
__device__ __forceinline__ void gemm_frag16(uint32_t aAddr,
                                            const __half* __restrict__ wf,
                                            float (*acc)[4]) {
  uint2 breg[2][NT];
#pragma unroll
  for (int n = 0; n < NT; n++) breg[0][n] = *(const uint2*)(wf + n * 2048);
#pragma unroll
  for (int n = 0; n < NT; n++) breg[1][n] = *(const uint2*)(wf + n * 2048 + 128);
#pragma unroll
  for (int k = 0; k < 16; k++) {
    uint32_t a0, a1, a2, a3;
    ldsm4(a0, a1, a2, a3, aAddr + (uint32_t)(k * 32));
#pragma unroll
    for (int n = 0; n < NT; n++) {
      uint2 b = breg[k & 1][n];
      mma16816(acc[n], a0, a1, a2, a3, b.x, b.y);
    }
    if (k + 2 < 16) {
#pragma unroll
      for (int n = 0; n < NT; n++)
        breg[k & 1][n] = *(const uint2*)(wf + n * 2048 + (k + 2) * 128);
    }
  }
}

__device__ __forceinline__ void row_stats(const float* __restrict__ row, int lane,
                                          float v[8], float& mean, float& rstd) {
  const float4* r4 = (const float4*)row;
  float4 a = r4[lane * 2], b = r4[lane * 2 + 1];
  v[0] = a.x; v[1] = a.y; v[2] = a.z; v[3] = a.w;
  v[4] = b.x; v[5] = b.y; v[6] = b.z; v[7] = b.w;
  float s = 0.f, s2 = 0.f;
#pragma unroll
  for (int j = 0; j < 8; j++) { s += v[j]; s2 += v[j] * v[j]; }
#pragma unroll
  for (int o = 16; o > 0; o >>= 1) {
    s += __shfl_xor_sync(0xffffffffu, s, o);
    s2 += __shfl_xor_sync(0xffffffffu, s2, o);
  }
  mean = s * (1.f / 256.f);
  rstd = rsqrtf(s2 * (1.f / 256.f) - mean * mean + 1e-5f);
}

__device__ __forceinline__ void ln_to_half(const float* __restrict__ xs,
                                           __half* __restrict__ dst,
                                           const float* __restrict__ g,
                                           const float* __restrict__ bt, int tid) {
  int warp = tid >> 5, lane = tid & 31;
#pragma unroll
  for (int i = 0; i < 4; i++) {
    int r = warp * 4 + i;
    float v[8], mean, rstd;
    row_stats(xs + r * XSD, lane, v, mean, rstd);
    __half2* d2 = (__half2*)(dst + r * HS + lane * 8);
#pragma unroll
    for (int j = 0; j < 4; j++) {
      int c = lane * 8 + 2 * j;
      d2[j] = __floats2half2_rn((v[2 * j] - mean) * rstd * g[c] + bt[c],
                                (v[2 * j + 1] - mean) * rstd * g[c + 1] + bt[c + 1]);
    }
  }
}

__device__ __forceinline__ void ln_inplace(float* __restrict__ xs,
                                           const float* __restrict__ g,
                                           const float* __restrict__ bt, int tid) {
  int warp = tid >> 5, lane = tid & 31;
#pragma unroll
  for (int i = 0; i < 4; i++) {
    int r = warp * 4 + i;
    float v[8], mean, rstd;
    row_stats(xs + r * XSD, lane, v, mean, rstd);
#pragma unroll
    for (int j = 0; j < 8; j++) {
      int c = lane * 8 + j;
      xs[r * XSD + c] = (v[j] - mean) * rstd * g[c] + bt[c];
    }
  }
}

__global__ void __launch_bounds__(kNT, 2) fused_kernel(
    const float* __restrict__ global_emb, const float* __restrict__ pert_emb,
    const float* __restrict__ sym_feat, const float* __restrict__ ppi_feat,
    const float* __restrict__ sym_W, const float* __restrict__ sym_b,
    const float* __restrict__ sym_ln_g, const float* __restrict__ sym_ln_b,
    const float* __restrict__ tte, const float* __restrict__ bqkv,
    const float* __restrict__ bo, const float* __restrict__ ln1_g,
    const float* __restrict__ ln1_b, const float* __restrict__ ln2_g,
    const float* __restrict__ ln2_b, const float* __restrict__ b1,
    const float* __restrict__ b2, const float* __restrict__ final_g,
    const float* __restrict__ final_b, const float* __restrict__ out_g,
    const float* __restrict__ out_b, float* __restrict__ out) {
  extern __shared__ char smem[];
  float* xs = (float*)(smem + XO);
  __half* hA = (__half*)(smem + HAO);
  __half* qk16 = (__half*)(smem + QOF);
  __half* oB = (__half*)(smem + OOF);

  const int tid = threadIdx.x, warp = tid >> 5, lane = tid & 31;
  const int gb0 = blockIdx.x * kMB;
  const uint32_t hA_u = smem_u32(hA), oB_u = smem_u32(oB);

  // ---- initial x: tokens 0,1,3 + tte; stage sym_feat ----
#pragma unroll
  for (int i = 0; i < 8; i++) {
    int u = tid + kNT * i;
    int b = u >> 8, c = u & 255;
    xs[(b * 4 + 0) * XSD + c] = global_emb[(size_t)(gb0 + b) * 256 + c] + tte[c];
    xs[(b * 4 + 1) * XSD + c] = pert_emb[(size_t)(gb0 + b) * 256 + c] + tte[256 + c];
    xs[(b * 4 + 3) * XSD + c] = ppi_feat[(size_t)(gb0 + b) * 256 + c] + tte[768 + c];
  }
  {
    float* stage = (float*)qk16;
#pragma unroll
    for (int i = 0; i < 2; i++) {
      int u = tid + kNT * i;
      stage[u] = sym_feat[(size_t)gb0 * 64 + u];
    }
  }
  __syncthreads();
  {  // sym projection fp32
    const float* stage = (const float*)qk16;
#pragma unroll
    for (int i = 0; i < 8; i++) {
      int u = tid + kNT * i;
      int b = u >> 8, c = u & 255;
      const float* sf = stage + b * 64;
      float acc = sym_b[c];
#pragma unroll 8
      for (int k = 0; k < 64; k++) acc += sf[k] * sym_W[k * 256 + c];
      xs[(b * 4 + 2) * XSD + c] = acc;
    }
  }
  __syncthreads();
  {  // sym LN + tte
    int r = warp * 4 + 2;
    float v[8], mean, rstd;
    row_stats(xs + r * XSD, lane, v, mean, rstd);
#pragma unroll
    for (int j = 0; j < 8; j++) {
      int c = lane * 8 + j;
      xs[r * XSD + c] = (v[j] - mean) * rstd * sym_ln_g[c] + sym_ln_b[c] + tte[512 + c];
    }
  }
  __syncthreads();

  const int rb = lane >> 2;
  const int cl = 2 * (lane & 3);
  const int wr = warp >> 2, wc = warp & 3;   // 2 row-bands x 4 col-groups
  const uint32_t aOff =
      (uint32_t)(((16 * wr + (lane & 15)) * HS + ((lane >> 4) << 3)) << 1);

  for (int l = 0; l < kL; l++) {
    ln_to_half(xs, hA, ln1_g + l * 256, ln1_b + l * 256, tid);
    __syncthreads();

    // ========== QKV: 2 phases x 4 heads; warp = 16 rows x 96 cols ==========
    for (int p = 0; p < 2; p++) {
      const __half* qf =
          g_WqkvF + (size_t)l * 196608 + (size_t)(p * 48 + wc * 12) * 2048 + lane * 4;
      float acc[12][4];
#pragma unroll
      for (int i = 0; i < 12; i++)
#pragma unroll
        for (int j = 0; j < 4; j++) acc[i][j] = 0.f;
      gemm_frag16<12>(hA_u + aOff, qf, acc);

      // epilogue -> qk16 fp16 (+bias), gathered layout: [head&3][q|k|v]
      const float* bq = bqkv + l * 768;
#pragma unroll
      for (int n = 0; n < 12; n++) {
        int T = p * 48 + wc * 12 + n;
        int head = T / 12, jm = T % 12, part = jm >> 2, sub = jm & 3;
        int lcol = (head & 3) * 96 + part * 32 + sub * 8 + cl;
        int bc = part * 256 + head * 32 + sub * 8 + cl;
        float bv0 = bq[bc], bv1 = bq[bc + 1];
        int row = 16 * wr + rb;
        *(__half2*)(qk16 + row * QS + lcol) =
            __floats2half2_rn(acc[n][0] + bv0, acc[n][1] + bv1);
        *(__half2*)(qk16 + (row + 8) * QS + lcol) =
            __floats2half2_rn(acc[n][2] + bv0, acc[n][3] + bv1);
      }
      __syncthreads();

      // attention for 4 heads: one warp per sequence
      {
        const int bi = warp;
        const int qt = lane >> 3, kt = (lane >> 1) & 3, dh = lane & 1;
#pragma unroll
        for (int hh = 0; hh < 4; hh++) {
          const __half2* q2 = (const __half2*)(qk16 + (bi * 4 + qt) * QS + hh * 96 + dh * 16);
          const __half2* k2 = (const __half2*)(qk16 + (bi * 4 + kt) * QS + hh * 96 + 32 + dh * 16);
          const __half2* v2 = (const __half2*)(qk16 + (bi * 4 + kt) * QS + hh * 96 + 64 + dh * 16);
          float s = 0.f;
#pragma unroll
          for (int d = 0; d < 8; d++) {
            float2 qa = __half22float2(q2[d]), ka = __half22float2(k2[d]);
            s += qa.x * ka.x + qa.y * ka.y;
          }
          s += __shfl_xor_sync(0xffffffffu, s, 1);
          s *= 0.17677669529663687f;
          float mx = fmaxf(s, __shfl_xor_sync(0xffffffffu, s, 2));
          mx = fmaxf(mx, __shfl_xor_sync(0xffffffffu, mx, 4));
          float pr = expf(s - mx);
          float dn = pr + __shfl_xor_sync(0xffffffffu, pr, 2);
          dn += __shfl_xor_sync(0xffffffffu, dn, 4);
          pr /= dn;
          float pv[16];
#pragma unroll
          for (int d = 0; d < 8; d++) {
            float2 va = __half22float2(v2[d]);
            float x0 = pr * va.x, x1 = pr * va.y;
            x0 += __shfl_xor_sync(0xffffffffu, x0, 2);
            x1 += __shfl_xor_sync(0xffffffffu, x1, 2);
            x0 += __shfl_xor_sync(0xffffffffu, x0, 4);
            x1 += __shfl_xor_sync(0xffffffffu, x1, 4);
            pv[2 * d] = x0; pv[2 * d + 1] = x1;
          }
          if (kt == 0) {
            __half2* o2 = (__half2*)(oB + (bi * 4 + qt) * HS + (p * 4 + hh) * 32 + dh * 16);
#pragma unroll
            for (int d = 0; d < 8; d++)
              o2[d] = __floats2half2_rn(pv[2 * d], pv[2 * d + 1]);
          }
        }
      }
      __syncthreads();
    }

    // ========== square GEMMs: warp = 16 rows x 64 cols ==========
#pragma unroll 1
    for (int gg = 0; gg < 3; gg++) {
      const __half* wf =
          ((gg == 0) ? g_WoF : (gg == 1) ? g_W1F : g_W2F) + (size_t)l * 65536 +
          (size_t)(wc * 8) * 2048 + lane * 4;
      const uint32_t aBase = (gg == 1) ? hA_u : oB_u;
      float acc[8][4];
#pragma unroll
      for (int i = 0; i < 8; i++)
#pragma unroll
        for (int j = 0; j < 4; j++) acc[i][j] = 0.f;
      gemm_frag16<8>(aBase + aOff, wf, acc);

      if (gg == 1) {  // GELU -> oB
        const float* bb = b1 + l * 256;
#pragma unroll
        for (int n = 0; n < 8; n++) {
          int col = wc * 64 + n * 8 + cl;
          float bv0 = bb[col], bv1 = bb[col + 1];
#pragma unroll
          for (int q = 0; q < 2; q++) {
            int row = 16 * wr + q * 8 + rb;
            float v0 = acc[n][2 * q] + bv0, v1 = acc[n][2 * q + 1] + bv1;
            *(__half2*)(oB + row * HS + col) = __floats2half2_rn(
                0.5f * v0 * (1.0f + erff(v0 * 0.7071067811865475f)),
                0.5f * v1 * (1.0f + erff(v1 * 0.7071067811865475f)));
          }
        }
      } else {  // residual add
        const float* bb = (gg == 0) ? bo + l * 256 : b2 + l * 256;
#pragma unroll
        for (int n = 0; n < 8; n++) {
          int col = wc * 64 + n * 8 + cl;
          float bv0 = bb[col], bv1 = bb[col + 1];
#pragma unroll
          for (int q = 0; q < 2; q++) {
            int row = 16 * wr + q * 8 + rb;
            xs[row * XSD + col] += acc[n][2 * q] + bv0;
            xs[row * XSD + col + 1] += acc[n][2 * q + 1] + bv1;
          }
        }
      }
      __syncthreads();
      if (gg == 0) {  // LN2 -> hA for W1
        ln_to_half(xs, hA, ln2_g + l * 256, ln2_b + l * 256, tid);
        __syncthreads();
      }
    }
  }

  // ---- final LN, mean over 4 tokens, output LN ----
  ln_inplace(xs, final_g, final_b, tid);
  __syncthreads();
  {
    int b = warp;
    const float* base = xs + b * 4 * XSD;
    float v[8], s = 0.f, s2 = 0.f;
#pragma unroll
    for (int j = 0; j < 8; j++) {
      int c = lane * 8 + j;
      float m = 0.25f * (base[c] + base[XSD + c] + base[2 * XSD + c] + base[3 * XSD + c]);
      v[j] = m; s += m; s2 += m * m;
    }
#pragma unroll
    for (int o = 16; o > 0; o >>= 1) {
      s += __shfl_xor_sync(0xffffffffu, s, o);
      s2 += __shfl_xor_sync(0xffffffffu, s2, o);
    }
    float mean = s * (1.f / 256.f);
    float rstd = rsqrtf(s2 * (1.f / 256.f) - mean * mean + 1e-5f);
#pragma unroll
    for (int j = 0; j < 8; j++) {
      int c = lane * 8 + j;
      out[(size_t)(gb0 + b) * 256 + c] = (v[j] - mean) * rstd * out_g[c] + out_b[c];
    }
  }
}

extern "C" void kernel_launch(void* const* d_in, const int* in_sizes, int n_in,
                              void* d_out, int out_size) {
  (void)in_sizes; (void)n_in; (void)out_size;
  const float* global_emb = (const float*)d_in[0];
  const float* pert_emb   = (const float*)d_in[1];
  const float* sym_feat   = (const float*)d_in[2];
  const float* ppi_feat   = (const float*)d_in[3];
  const float* sym_W      = (const float*)d_in[4];
  const float* sym_b      = (const float*)d_in[5];
  const float* sym_ln_g   = (const float*)d_in[6];
  const float* sym_ln_b   = (const float*)d_in[7];
  const float* tte        = (const float*)d_in[8];
  const float* Wqkv       = (const float*)d_in[9];
  const float* bqkv       = (const float*)d_in[10];
  const float* Wo         = (const float*)d_in[11];
  const float* bo         = (const float*)d_in[12];
  const float* ln1_g      = (const float*)d_in[13];
  const float* ln1_b      = (const float*)d_in[14];
  const float* ln2_g      = (const float*)d_in[15];
  const float* ln2_b      = (const float*)d_in[16];
  const float* W1         = (const float*)d_in[17];
  const float* b1         = (const float*)d_in[18];
  const float* W2         = (const float*)d_in[19];
  const float* b2         = (const float*)d_in[20];
  const float* final_g    = (const float*)d_in[21];
  const float* final_b    = (const float*)d_in[22];
  const float* out_g      = (const float*)d_in[23];
  const float* out_b      = (const float*)d_in[24];

  static bool attr_done = false;
  if (!attr_done) {
    cudaFuncSetAttribute(fused_kernel, cudaFuncAttributeMaxDynamicSharedMemorySize,
                         SMEM_BYTES);
    attr_done = true;
  }

  const int NSLOTS = kL * 96 * 16 * 32 + 3 * kL * 32 * 16 * 32;  // 294912
  prep_weights_kernel<<<(NSLOTS + 255) / 256, 256>>>(Wqkv, Wo, W1, W2);
  fused_kernel<<<kB / kMB, kNT, SMEM_BYTES>>>(
      global_emb, pert_emb, sym_feat, ppi_feat, sym_W, sym_b, sym_ln_g, sym_ln_b,
      tte, bqkv, bo, ln1_g, ln1_b, ln2_g, ln2_b, b1, b2, final_g, final_b, out_g,
      out_b, (float*)d_out);
}